// round 13
// baseline (speedup 1.0000x reference)
#include <cuda_runtime.h>
#include <cstdint>
#include <math.h>

#define B_GRAPHS 512
#define N_NODES  128
#define F_OUT    256
#define HEADS    4
#define HID      64
#define M_TOT    (B_GRAPHS * N_NODES)   // 65536
#define LOG2E    1.4426950408889634f

__device__ float g_X[(size_t)M_TOT * F_OUT];
__device__ float g_Y[(size_t)M_TOT * F_OUT];
__device__ float g_Wt[3][256 * 256];

// ---------------------------------------------------------------------------
#define CP_ASYNC16(dst, src) \
    asm volatile("cp.async.cg.shared.global [%0], [%1], 16;" \
        :: "r"((uint32_t)(dst)), "l"(src) : "memory")
#define CP_COMMIT() asm volatile("cp.async.commit_group;" ::: "memory")
#define CP_WAIT0()  asm volatile("cp.async.wait_group 0;" ::: "memory")

__device__ __forceinline__ uint32_t smem_to_u32(const void* p) {
    uint32_t a;
    asm("{ .reg .u64 t; cvta.to.shared.u64 t, %1; cvt.u32.u64 %0, t; }"
        : "=r"(a) : "l"(p));
    return a;
}

__device__ __forceinline__ uint32_t tf32r(float f) {
    uint32_t u;
    asm("cvt.rna.tf32.f32 %0, %1;" : "=r"(u) : "f"(f));
    return u;
}

__device__ __forceinline__ float ex2(float x) {
    float r;
    asm("ex2.approx.f32 %0, %1;" : "=f"(r) : "f"(x));
    return r;
}

__device__ __forceinline__ void ldsm_x4(
    uint32_t& r0, uint32_t& r1, uint32_t& r2, uint32_t& r3, uint32_t addr)
{
    asm volatile("ldmatrix.sync.aligned.m8n8.x4.shared.b16 {%0,%1,%2,%3}, [%4];"
        : "=r"(r0), "=r"(r1), "=r"(r2), "=r"(r3) : "r"(addr));
}

__device__ __forceinline__ void mma_tf32(
    float& d0, float& d1, float& d2, float& d3,
    uint32_t a0, uint32_t a1, uint32_t a2, uint32_t a3,
    uint32_t b0, uint32_t b1)
{
    asm volatile(
        "mma.sync.aligned.m16n8k8.row.col.f32.tf32.tf32.f32 "
        "{%0,%1,%2,%3}, {%4,%5,%6,%7}, {%8,%9}, {%0,%1,%2,%3};"
        : "+f"(d0), "+f"(d1), "+f"(d2), "+f"(d3)
        : "r"(a0), "r"(a1), "r"(a2), "r"(a3), "r"(b0), "r"(b1));
}

__device__ __forceinline__ float leaky(float a) {
    return fmaxf(a, 0.2f * a);
}

// ---------------------------------------------------------------------------
__global__ __launch_bounds__(256) void round_x_kernel(
    const float* __restrict__ x, float* __restrict__ xr)
{
    int t = blockIdx.x * 256 + threadIdx.x;
    float4 v = ((const float4*)x)[t];
    uint4 o = make_uint4(tf32r(v.x), tf32r(v.y), tf32r(v.z), tf32r(v.w));
    ((uint4*)xr)[t] = o;
}

__global__ __launch_bounds__(256) void transpose_all_kernel(
    const float* __restrict__ W0, const float* __restrict__ W1,
    const float* __restrict__ W2, float* __restrict__ Wt)
{
    int t = blockIdx.x * 256 + threadIdx.x;
    uint32_t* o = (uint32_t*)Wt;
    if (t < 128 * 256) {
        int k = t >> 8, n = t & 255;
        o[(size_t)n * 128 + k] = tf32r(W0[t]);
    } else if (t < 128 * 256 + 256 * 256) {
        int t2 = t - 128 * 256;
        int k = t2 >> 8, n = t2 & 255;
        o[65536 + (size_t)n * 256 + k] = tf32r(W1[t2]);
    } else {
        int t3 = t - 128 * 256 - 256 * 256;
        int k = t3 >> 8, n = t3 & 255;
        o[131072 + (size_t)n * 256 + k] = tf32r(W2[t3]);
    }
}

// ===========================================================================
// Fused layer kernel. 512 thr, 2 CTAs/SM. Single-barrier cp.async pipeline.
// ===========================================================================
#define PSTR 132
#define OFF_SVP  3072                  // [4][128] partials
#define OFF_DVP  5120
#define OFF_SVI  7168                  // float2 [2][16][4] interleaved scores
#define OFF_DV   8192                  // [2][128] scaled
#define OFF_SMX  9216                  // [2]
#define OFF_QP   9472                  // [16][128]
#define OFF_QV   17664                 // [2][128]
#define OFF_U    18944
#define AS_STG   18432                 // 128 rows * 144B
#define LAYER_SMEM (OFF_U + 4 * AS_STG)   // 92672 -> 2 CTAs/SM
// Ht [128][132] f32 (67584 B) overlaps the 4 stage buffers in U.

__global__ __launch_bounds__(512, 2) void layer_kernel(
    const float* __restrict__ A, const float* __restrict__ Wt,
    const float* __restrict__ att_src, const float* __restrict__ att_dst,
    const float* __restrict__ bias_g,
    float* __restrict__ X, float* __restrict__ out_final,
    int K, int last)
{
    extern __shared__ char sm[];
    uint32_t sb = smem_to_u32(sm);
    float* atts  = (float*)(sm);
    float* attd  = (float*)(sm + 1024);
    float* biass = (float*)(sm + 2048);
    float* svp   = (float*)(sm + OFF_SVP);
    float* dvp   = (float*)(sm + OFF_DVP);
    float2* svI  = (float2*)(sm + OFF_SVI);
    float* dv    = (float*)(sm + OFF_DV);
    float* smaxs = (float*)(sm + OFF_SMX);
    float* qpart = (float*)(sm + OFF_QP);
    float* qv    = (float*)(sm + OFF_QV);
    uint32_t* Htu = (uint32_t*)(sm + OFF_U);

    const int tid = threadIdx.x;
    const int warp = tid >> 5, lane = tid & 31;
    const int gid = lane >> 2, tig = lane & 3;
    const int wm = warp & 3, wn = warp >> 2;
    const int b = blockIdx.x, m0 = b * 128;
    const int t4 = lane >> 3, r8 = lane & 7;

    if (tid < 256) {
        atts[tid]  = att_src[tid];
        attd[tid]  = att_dst[tid];
        biass[tid] = bias_g[tid];
    }

    // GEMM ldmatrix offsets
    uint32_t aoff[2], boff[2];
#pragma unroll
    for (int mt = 0; mt < 2; mt++)
        aoff[mt] = (uint32_t)((wm * 32 + mt * 16 + (t4 & 1) * 8 + r8) * 144
                              + (t4 >> 1) * 16);
#pragma unroll
    for (int pr = 0; pr < 2; pr++)
        boff[pr] = (uint32_t)((wn * 32 + pr * 16 + (t4 >> 1) * 8 + r8) * 144
                              + (t4 & 1) * 16);
    // attention: warp = (hl head, wm8 row-group); 16 rows x 64 cols
    const int wm8 = warp & 7, hl = warp >> 3;
    const uint32_t hoffA = (uint32_t)(((t4 >> 1) * 8 + r8) * (PSTR * 4)
                                      + (t4 & 1) * 16);

    const int NC = K >> 5;

#pragma unroll 1
    for (int nh = 0; nh < 2; nh++) {
        // ---------------- GEMM half: 128 x 128 ----------------
        float acc[2][4][4];
#pragma unroll
        for (int mt = 0; mt < 2; mt++)
#pragma unroll
            for (int nt = 0; nt < 4; nt++)
#pragma unroll
                for (int c = 0; c < 4; c++) acc[mt][nt][c] = 0.f;

        auto load_chunk = [&](int k0, int stage) {
            uint32_t ab = sb + OFF_U + stage * AS_STG;
            uint32_t bb = sb + OFF_U + 2 * AS_STG + stage * AS_STG;
#pragma unroll
            for (int i = 0; i < 2; i++) {
                int g = tid + i * 512;
                int row = g >> 3, c = g & 7;
                CP_ASYNC16(ab + row * 144 + c * 16,
                           A + (size_t)(m0 + row) * K + k0 + c * 4);
            }
#pragma unroll
            for (int i = 0; i < 2; i++) {
                int g = tid + i * 512;
                int row = g >> 3, c = g & 7;
                CP_ASYNC16(bb + row * 144 + c * 16,
                           Wt + (size_t)(nh * 128 + row) * K + k0 + c * 4);
            }
        };

        load_chunk(0, 0);
        CP_COMMIT();

        // Single-barrier 2-stage pipeline:
        //   WAIT0 -> barrier -> issue loads(c+1, s^1) -> MMA(stage s)
        // Barrier(c) orders prior MMA reads of stage s^1 (iter c-1) before
        // this iteration's cp.async writes to it; WAIT0+barrier ensure all
        // warps' chunk-c data landed before any MMA(c).
        for (int c = 0; c < NC; c++) {
            CP_WAIT0();
            __syncthreads();
            if (c + 1 < NC) {
                load_chunk((c + 1) << 5, (c + 1) & 1);
                CP_COMMIT();
            }

            uint32_t as_b = sb + OFF_U + (c & 1) * AS_STG;
            uint32_t bs_b = sb + OFF_U + 2 * AS_STG + (c & 1) * AS_STG;
#pragma unroll
            for (int kk = 0; kk < 4; kk++) {
                uint32_t a[2][4];
#pragma unroll
                for (int mt = 0; mt < 2; mt++)
                    ldsm_x4(a[mt][0], a[mt][1], a[mt][2], a[mt][3],
                            as_b + aoff[mt] + kk * 32);
                uint32_t bf[4][2];
#pragma unroll
                for (int pr = 0; pr < 2; pr++)
                    ldsm_x4(bf[pr * 2][0], bf[pr * 2][1],
                            bf[pr * 2 + 1][0], bf[pr * 2 + 1][1],
                            bs_b + boff[pr] + kk * 32);
#pragma unroll
                for (int mt = 0; mt < 2; mt++)
#pragma unroll
                    for (int nt = 0; nt < 4; nt++)
                        mma_tf32(acc[mt][nt][0], acc[mt][nt][1],
                                 acc[mt][nt][2], acc[mt][nt][3],
                                 a[mt][0], a[mt][1], a[mt][2], a[mt][3],
                                 bf[nt][0], bf[nt][1]);
            }
        }
        __syncthreads();   // all MMA stage reads done before epilogue
                           // overwrites the U region (Htu)

        // ---------------- epilogue: Ht (transposed tf32) + score partials ---
        const int hl_w = wn >> 1;
#pragma unroll
        for (int mt = 0; mt < 2; mt++) {
#pragma unroll
            for (int h2 = 0; h2 < 2; h2++) {
                int rl = wm * 32 + mt * 16 + gid + 8 * h2;
                float s = 0.f, d = 0.f;
#pragma unroll
                for (int nt = 0; nt < 4; nt++) {
                    int cl = (wn & 1) * 32 + nt * 8 + tig * 2;
                    int gc = nh * 128 + wn * 32 + nt * 8 + tig * 2;
                    float v0 = acc[mt][nt][h2 * 2], v1 = acc[mt][nt][h2 * 2 + 1];
                    s = fmaf(v0, atts[gc], s);  s = fmaf(v1, atts[gc + 1], s);
                    d = fmaf(v0, attd[gc], d);  d = fmaf(v1, attd[gc + 1], d);
                    Htu[(hl_w * 64 + cl) * PSTR + rl]     = tf32r(v0);
                    Htu[(hl_w * 64 + cl + 1) * PSTR + rl] = tf32r(v1);
                }
                s += __shfl_xor_sync(0xffffffffu, s, 1);
                s += __shfl_xor_sync(0xffffffffu, s, 2);
                d += __shfl_xor_sync(0xffffffffu, d, 1);
                d += __shfl_xor_sync(0xffffffffu, d, 2);
                if (tig == 0) {
                    svp[wn * 128 + rl] = s;
                    dvp[wn * 128 + rl] = d;
                }
            }
        }
        __syncthreads();

        // reduce partials (scaled by log2e) -> svI (interleaved) / dv / smaxs
        if (tid < 256) {
            int hh = tid >> 7, j = tid & 127;
            float s2 = (svp[(2 * hh) * 128 + j]
                        + svp[(2 * hh + 1) * 128 + j]) * LOG2E;
            float d2 = (dvp[(2 * hh) * 128 + j]
                        + dvp[(2 * hh + 1) * 128 + j]) * LOG2E;
            dv[hh * 128 + j] = d2;
            int kk = j >> 3, r = j & 7;
            ((float*)svI)[((hh * 16 + kk) * 4 + (r & 3)) * 2 + (r >> 2)] = s2;
        } else if (tid < 320) {
            int t = tid - 256, hh = t >> 5, l = t & 31;
            float m = -1e30f;
#pragma unroll
            for (int q = 0; q < 4; q++) {
                int j = l + q * 32;
                m = fmaxf(m, svp[(2 * hh) * 128 + j]
                             + svp[(2 * hh + 1) * 128 + j]);
            }
#pragma unroll
            for (int off = 16; off; off >>= 1)
                m = fmaxf(m, __shfl_xor_sync(0xffffffffu, m, off));
            if (l == 0) smaxs[hh] = m * LOG2E;
        }
        __syncthreads();

        // ---------------- attention: 16x64 warp tiles, exp once ------------
        {
            const int gh = nh * 2 + hl;
            const uint32_t ht_b = sb + OFF_U + (uint32_t)hl * (64 * PSTR * 4);
            const float2* svh = svI + hl * 64;   // [kk][tig]

            const int rr0 = wm8 * 16 + gid;
            const float dd0 = dv[hl * 128 + rr0];
            const float dd1 = dv[hl * 128 + rr0 + 8];
            const float smx = smaxs[hl];
            const float mx0 = leaky(smx + dd0);   // exact row max (monotone)
            const float mx1 = leaky(smx + dd1);

            if (!last) {
                float oacc[8][4];
#pragma unroll
                for (int nt = 0; nt < 8; nt++)
#pragma unroll
                    for (int c = 0; c < 4; c++) oacc[nt][c] = 0.f;
                float sum0 = 0.f, sum1 = 0.f;

#pragma unroll
                for (int kk = 0; kk < 16; kk++) {
                    float2 sj = svh[kk * 4 + tig];
                    float p00 = ex2(leaky(sj.x + dd0) - mx0);
                    float p10 = ex2(leaky(sj.x + dd1) - mx1);
                    float p01 = ex2(leaky(sj.y + dd0) - mx0);
                    float p11 = ex2(leaky(sj.y + dd1) - mx1);
                    sum0 += p00 + p01;
                    sum1 += p10 + p11;
                    uint32_t a0 = tf32r(p00), a1 = tf32r(p10);
                    uint32_t a2 = tf32r(p01), a3 = tf32r(p11);
#pragma unroll
                    for (int pr = 0; pr < 4; pr++) {
                        uint32_t b0, b1, b2, b3;
                        ldsm_x4(b0, b1, b2, b3,
                                ht_b + pr * (16 * PSTR * 4) + hoffA + kk * 32);
                        mma_tf32(oacc[pr * 2][0], oacc[pr * 2][1],
                                 oacc[pr * 2][2], oacc[pr * 2][3],
                                 a0, a1, a2, a3, b0, b1);
                        mma_tf32(oacc[pr * 2 + 1][0], oacc[pr * 2 + 1][1],
                                 oacc[pr * 2 + 1][2], oacc[pr * 2 + 1][3],
                                 a0, a1, a2, a3, b2, b3);
                    }
                }
                sum0 += __shfl_xor_sync(0xffffffffu, sum0, 1);
                sum0 += __shfl_xor_sync(0xffffffffu, sum0, 2);
                sum1 += __shfl_xor_sync(0xffffffffu, sum1, 1);
                sum1 += __shfl_xor_sync(0xffffffffu, sum1, 2);
                float inv0 = 1.0f / sum0, inv1 = 1.0f / sum1;

                float* o0 = X + ((size_t)m0 + rr0) * 256 + gh * 64;
                float* o1 = X + ((size_t)m0 + rr0 + 8) * 256 + gh * 64;
#pragma unroll
                for (int nt = 0; nt < 8; nt++) {
                    int col = nt * 8 + tig * 2;
                    float bb0 = biass[gh * 64 + col];
                    float bb1 = biass[gh * 64 + col + 1];
                    float2 v0 = make_float2(
                        __uint_as_float(tf32r(fmaf(oacc[nt][0], inv0, bb0))),
                        __uint_as_float(tf32r(fmaf(oacc[nt][1], inv0, bb1))));
                    float2 v1 = make_float2(
                        __uint_as_float(tf32r(fmaf(oacc[nt][2], inv1, bb0))),
                        __uint_as_float(tf32r(fmaf(oacc[nt][3], inv1, bb1))));
                    *(float2*)&o0[col] = v0;
                    *(float2*)&o1[col] = v1;
                }
            } else {
                // q path: q_j = sum_i e_ij / r_i (no MMA)
                float sum0 = 0.f, sum1 = 0.f;
#pragma unroll
                for (int kk = 0; kk < 16; kk++) {
                    float2 sj = svh[kk * 4 + tig];
                    sum0 += ex2(leaky(sj.x + dd0) - mx0)
                          + ex2(leaky(sj.y + dd0) - mx0);
                    sum1 += ex2(leaky(sj.x + dd1) - mx1)
                          + ex2(leaky(sj.y + dd1) - mx1);
                }
                sum0 += __shfl_xor_sync(0xffffffffu, sum0, 1);
                sum0 += __shfl_xor_sync(0xffffffffu, sum0, 2);
                sum1 += __shfl_xor_sync(0xffffffffu, sum1, 1);
                sum1 += __shfl_xor_sync(0xffffffffu, sum1, 2);
                float inv0 = 1.0f / sum0, inv1 = 1.0f / sum1;

#pragma unroll
                for (int kk = 0; kk < 16; kk++) {
                    float2 sj = svh[kk * 4 + tig];
                    float qc0 = ex2(leaky(sj.x + dd0) - mx0) * inv0
                              + ex2(leaky(sj.x + dd1) - mx1) * inv1;
                    float qc1 = ex2(leaky(sj.y + dd0) - mx0) * inv0
                              + ex2(leaky(sj.y + dd1) - mx1) * inv1;
                    qc0 += __shfl_xor_sync(0xffffffffu, qc0, 4);
                    qc0 += __shfl_xor_sync(0xffffffffu, qc0, 8);
                    qc0 += __shfl_xor_sync(0xffffffffu, qc0, 16);
                    qc1 += __shfl_xor_sync(0xffffffffu, qc1, 4);
                    qc1 += __shfl_xor_sync(0xffffffffu, qc1, 8);
                    qc1 += __shfl_xor_sync(0xffffffffu, qc1, 16);
                    if (gid == 0) {
                        qpart[(hl * 8 + wm8) * 128 + kk * 8 + tig]     = qc0;
                        qpart[(hl * 8 + wm8) * 128 + kk * 8 + tig + 4] = qc1;
                    }
                }
            }
        }

        if (last) {
            __syncthreads();
            if (tid < 256) {
                int hh = tid >> 7, cc = tid & 127;
                float qs = 0.f;
#pragma unroll
                for (int w = 0; w < 8; w++)
                    qs += qpart[(hh * 8 + w) * 128 + cc];
                qv[hh * 128 + cc] = qs;
            }
            __syncthreads();
#pragma unroll 1
            for (int hq = 0; hq < 2; hq++) {
                int c = tid >> 3, t8 = tid & 7;
                float a3 = 0.f;
#pragma unroll 4
                for (int jj = 0; jj < 16; jj++) {
                    int j = t8 * 16 + jj;
                    a3 += qv[hq * 128 + j] *
                          __uint_as_float(Htu[(hq * 64 + c) * PSTR + j]);
                }
                a3 += __shfl_xor_sync(0xffffffffu, a3, 1);
                a3 += __shfl_xor_sync(0xffffffffu, a3, 2);
                a3 += __shfl_xor_sync(0xffffffffu, a3, 4);
                int gho = nh * 2 + hq;
                if (t8 == 0)
                    out_final[(size_t)b * 256 + gho * 64 + c] =
                        a3 + 128.f * biass[gho * 64 + c];
            }
        }
        __syncthreads();   // Ht dead; next half may overwrite staging
    } // nh
}

// ---------------------------------------------------------------------------
extern "C" void kernel_launch(void* const* d_in, const int* in_sizes, int n_in,
                              void* d_out, int out_size)
{
    const float* x = (const float*)d_in[0];
    const float* W[3]    = {(const float*)d_in[2], (const float*)d_in[6],  (const float*)d_in[10]};
    const float* asv[3]  = {(const float*)d_in[3], (const float*)d_in[7],  (const float*)d_in[11]};
    const float* adv[3]  = {(const float*)d_in[4], (const float*)d_in[8],  (const float*)d_in[12]};
    const float* bias[3] = {(const float*)d_in[5], (const float*)d_in[9],  (const float*)d_in[13]};

    float *pX, *pY, *pWt;
    cudaGetSymbolAddress((void**)&pX, g_X);
    cudaGetSymbolAddress((void**)&pY, g_Y);
    cudaGetSymbolAddress((void**)&pWt, g_Wt);

    cudaFuncSetAttribute(layer_kernel,
                         cudaFuncAttributeMaxDynamicSharedMemorySize, LAYER_SMEM);

    transpose_all_kernel<<<640, 256>>>(W[0], W[1], W[2], pWt);
    round_x_kernel<<<8192, 256>>>(x, pY);

    const float* in_buf[3]  = {pY, pX, pY};
    float*       out_buf[3] = {pX, pY, nullptr};

    for (int l = 0; l < 3; l++) {
        const int K = (l == 0) ? 128 : 256;
        const float* Wtl = pWt + (size_t)l * 65536;
        layer_kernel<<<512, 512, LAYER_SMEM>>>(
            in_buf[l], Wtl, asv[l], adv[l], bias[l],
            out_buf[l], (float*)d_out, K, l == 2);
    }
}

// round 14
// speedup vs baseline: 1.3789x; 1.3789x over previous
#include <cuda_runtime.h>
#include <cuda_fp16.h>
#include <cstdint>
#include <math.h>

#define B_GRAPHS 512
#define N_NODES  128
#define F_OUT    256
#define HEADS    4
#define HID      64
#define M_TOT    (B_GRAPHS * N_NODES)   // 65536
#define LOG2E    1.4426950408889634f

__device__ __half g_X[(size_t)M_TOT * F_OUT];   // activations, fp16
__device__ __half g_Y[(size_t)M_TOT * F_OUT];
__device__ __half g_Wt[3][256 * 256];           // transposed weights [n][k], fp16

// ---------------------------------------------------------------------------
#define CP_ASYNC16(dst, src) \
    asm volatile("cp.async.cg.shared.global [%0], [%1], 16;" \
        :: "r"((uint32_t)(dst)), "l"(src) : "memory")
#define CP_COMMIT() asm volatile("cp.async.commit_group;" ::: "memory")
#define CP_WAIT0()  asm volatile("cp.async.wait_group 0;" ::: "memory")

__device__ __forceinline__ uint32_t smem_to_u32(const void* p) {
    uint32_t a;
    asm("{ .reg .u64 t; cvta.to.shared.u64 t, %1; cvt.u32.u64 %0, t; }"
        : "=r"(a) : "l"(p));
    return a;
}

__device__ __forceinline__ float ex2(float x) {
    float r;
    asm("ex2.approx.f32 %0, %1;" : "=f"(r) : "f"(x));
    return r;
}

// pack two floats -> f16x2 (lo = first arg)
__device__ __forceinline__ uint32_t h2pack(float lo, float hi) {
    uint32_t d;
    asm("cvt.rn.f16x2.f32 %0, %1, %2;" : "=r"(d) : "f"(hi), "f"(lo));
    return d;
}

__device__ __forceinline__ void ldsm_x4(
    uint32_t& r0, uint32_t& r1, uint32_t& r2, uint32_t& r3, uint32_t addr)
{
    asm volatile("ldmatrix.sync.aligned.m8n8.x4.shared.b16 {%0,%1,%2,%3}, [%4];"
        : "=r"(r0), "=r"(r1), "=r"(r2), "=r"(r3) : "r"(addr));
}

__device__ __forceinline__ void mma_f16(
    float& d0, float& d1, float& d2, float& d3,
    uint32_t a0, uint32_t a1, uint32_t a2, uint32_t a3,
    uint32_t b0, uint32_t b1)
{
    asm volatile(
        "mma.sync.aligned.m16n8k16.row.col.f32.f16.f16.f32 "
        "{%0,%1,%2,%3}, {%4,%5,%6,%7}, {%8,%9}, {%0,%1,%2,%3};"
        : "+f"(d0), "+f"(d1), "+f"(d2), "+f"(d3)
        : "r"(a0), "r"(a1), "r"(a2), "r"(a3), "r"(b0), "r"(b1));
}

__device__ __forceinline__ float leaky(float a) {
    return fmaxf(a, 0.2f * a);
}

// ---------------------------------------------------------------------------
// Round layer-0 input to fp16.
// ---------------------------------------------------------------------------
__global__ __launch_bounds__(256) void round_x_kernel(
    const float* __restrict__ x, __half* __restrict__ xr)
{
    int t = blockIdx.x * 256 + threadIdx.x;
    float4 v = ((const float4*)x)[t];
    __half2* o = (__half2*)xr;
    o[t * 2]     = __floats2half2_rn(v.x, v.y);
    o[t * 2 + 1] = __floats2half2_rn(v.z, v.w);
}

// ---------------------------------------------------------------------------
// Transpose all three weight matrices to fp16 [n][k].
// ---------------------------------------------------------------------------
__global__ __launch_bounds__(256) void transpose_all_kernel(
    const float* __restrict__ W0, const float* __restrict__ W1,
    const float* __restrict__ W2, __half* __restrict__ Wt)
{
    int t = blockIdx.x * 256 + threadIdx.x;
    if (t < 128 * 256) {
        int k = t >> 8, n = t & 255;
        Wt[(size_t)n * 128 + k] = __float2half_rn(W0[t]);
    } else if (t < 128 * 256 + 256 * 256) {
        int t2 = t - 128 * 256;
        int k = t2 >> 8, n = t2 & 255;
        Wt[65536 + (size_t)n * 256 + k] = __float2half_rn(W1[t2]);
    } else {
        int t3 = t - 128 * 256 - 256 * 256;
        int k = t3 >> 8, n = t3 & 255;
        Wt[131072 + (size_t)n * 256 + k] = __float2half_rn(W2[t3]);
    }
}

// ===========================================================================
// Fused layer kernel, fp16 MMA (m16n8k16), 512 thr, 2 CTAs/SM.
// GEMM K-chunk 64 (stage 128 rows x 144B, fp16). Attention: register softmax
// -> f16x2 A-fragments; Ht fp16 [col][j] pitch 272B.
// ===========================================================================
#define HPITCH 272                    // Ht row pitch bytes (136 halves)
#define OFF_SVP  3072                 // [4][128] f32 partials
#define OFF_DVP  5120
#define OFF_SV   7168                 // [2][128] f32 scaled scores
#define OFF_DV   8192
#define OFF_SMX  9216                 // [2]
#define OFF_QP   9472                 // [16][128]
#define OFF_QV   17664                // [2][128]
#define OFF_U    18944
#define AS_STG   18432                // 128 rows * 144B (64 k fp16 + pad)
#define LAYER_SMEM (OFF_U + 4 * AS_STG)   // 92672 -> 2 CTAs/SM
// Ht: 128 cols x 272B = 34816 B, overlaps U.

__global__ __launch_bounds__(512, 2) void layer_kernel(
    const __half* __restrict__ A, const __half* __restrict__ Wt,
    const float* __restrict__ att_src, const float* __restrict__ att_dst,
    const float* __restrict__ bias_g,
    __half* __restrict__ X, float* __restrict__ out_final,
    int K, int last)
{
    extern __shared__ char sm[];
    uint32_t sb = smem_to_u32(sm);
    float* atts  = (float*)(sm);
    float* attd  = (float*)(sm + 1024);
    float* biass = (float*)(sm + 2048);
    float* svp   = (float*)(sm + OFF_SVP);
    float* dvp   = (float*)(sm + OFF_DVP);
    float* sv    = (float*)(sm + OFF_SV);
    float* dv    = (float*)(sm + OFF_DV);
    float* smaxs = (float*)(sm + OFF_SMX);
    float* qpart = (float*)(sm + OFF_QP);
    float* qv    = (float*)(sm + OFF_QV);
    __half* Ht16 = (__half*)(sm + OFF_U);

    const int tid = threadIdx.x;
    const int warp = tid >> 5, lane = tid & 31;
    const int gid = lane >> 2, tig = lane & 3;
    const int wm = warp & 3, wn = warp >> 2;
    const int b = blockIdx.x, m0 = b * 128;
    const int t4 = lane >> 3, r8 = lane & 7;

    if (tid < 256) {
        atts[tid]  = att_src[tid];
        attd[tid]  = att_dst[tid];
        biass[tid] = bias_g[tid];
    }

    // ldmatrix per-lane offsets (fp16 tiles, same formulas as tf32 version)
    uint32_t aoff[2], boff[2];
#pragma unroll
    for (int mt = 0; mt < 2; mt++)
        aoff[mt] = (uint32_t)((wm * 32 + mt * 16 + (t4 & 1) * 8 + r8) * 144
                              + (t4 >> 1) * 16);
#pragma unroll
    for (int pr = 0; pr < 2; pr++)
        boff[pr] = (uint32_t)((wn * 32 + pr * 16 + (t4 >> 1) * 8 + r8) * 144
                              + (t4 & 1) * 16);
    // attention: warp = (hl head, wm8 row-group); 16 rows x 64 cols
    const int wm8 = warp & 7, hl = warp >> 3;
    const uint32_t hoffA = (uint32_t)(((t4 >> 1) * 8 + r8) * HPITCH
                                      + (t4 & 1) * 16);

    const int NC = K >> 6;     // chunks of 64 k

#pragma unroll 1
    for (int nh = 0; nh < 2; nh++) {
        // ---------------- GEMM half: 128 x 128 (fp16) ----------------
        float acc[2][4][4];
#pragma unroll
        for (int mt = 0; mt < 2; mt++)
#pragma unroll
            for (int nt = 0; nt < 4; nt++)
#pragma unroll
                for (int c = 0; c < 4; c++) acc[mt][nt][c] = 0.f;

        auto load_chunk = [&](int k0, int stage) {
            uint32_t ab = sb + OFF_U + stage * AS_STG;
            uint32_t bb = sb + OFF_U + 2 * AS_STG + stage * AS_STG;
#pragma unroll
            for (int i = 0; i < 2; i++) {
                int g = tid + i * 512;
                int row = g >> 3, c = g & 7;
                CP_ASYNC16(ab + row * 144 + c * 16,
                           A + (size_t)(m0 + row) * K + k0 + c * 8);
            }
#pragma unroll
            for (int i = 0; i < 2; i++) {
                int g = tid + i * 512;
                int row = g >> 3, c = g & 7;
                CP_ASYNC16(bb + row * 144 + c * 16,
                           Wt + (size_t)(nh * 128 + row) * K + k0 + c * 8);
            }
        };

        load_chunk(0, 0);
        CP_COMMIT();

        for (int c = 0; c < NC; c++) {
            CP_WAIT0();
            __syncthreads();
            if (c + 1 < NC) {
                load_chunk((c + 1) << 6, (c + 1) & 1);
                CP_COMMIT();
            }

            uint32_t as_b = sb + OFF_U + (c & 1) * AS_STG;
            uint32_t bs_b = sb + OFF_U + 2 * AS_STG + (c & 1) * AS_STG;
#pragma unroll
            for (int kk = 0; kk < 4; kk++) {       // k16 steps within chunk
                uint32_t a[2][4];
#pragma unroll
                for (int mt = 0; mt < 2; mt++)
                    ldsm_x4(a[mt][0], a[mt][1], a[mt][2], a[mt][3],
                            as_b + aoff[mt] + kk * 32);
                uint32_t bf[4][2];
#pragma unroll
                for (int pr = 0; pr < 2; pr++)
                    ldsm_x4(bf[pr * 2][0], bf[pr * 2][1],
                            bf[pr * 2 + 1][0], bf[pr * 2 + 1][1],
                            bs_b + boff[pr] + kk * 32);
#pragma unroll
                for (int mt = 0; mt < 2; mt++)
#pragma unroll
                    for (int nt = 0; nt < 4; nt++)
                        mma_f16(acc[mt][nt][0], acc[mt][nt][1],
                                acc[mt][nt][2], acc[mt][nt][3],
                                a[mt][0], a[mt][1], a[mt][2], a[mt][3],
                                bf[nt][0], bf[nt][1]);
            }
        }
        __syncthreads();   // stage reads done before Ht overwrites U

        // ---------------- epilogue: Ht (fp16, transposed) + scores ---------
        const int hl_w = wn >> 1;
#pragma unroll
        for (int mt = 0; mt < 2; mt++) {
#pragma unroll
            for (int h2 = 0; h2 < 2; h2++) {
                int rl = wm * 32 + mt * 16 + gid + 8 * h2;
                float s = 0.f, d = 0.f;
#pragma unroll
                for (int nt = 0; nt < 4; nt++) {
                    int cl = (wn & 1) * 32 + nt * 8 + tig * 2;
                    int gc = nh * 128 + wn * 32 + nt * 8 + tig * 2;
                    float v0 = acc[mt][nt][h2 * 2], v1 = acc[mt][nt][h2 * 2 + 1];
                    s = fmaf(v0, atts[gc], s);  s = fmaf(v1, atts[gc + 1], s);
                    d = fmaf(v0, attd[gc], d);  d = fmaf(v1, attd[gc + 1], d);
                    Ht16[(hl_w * 64 + cl) * 136 + rl]     = __float2half_rn(v0);
                    Ht16[(hl_w * 64 + cl + 1) * 136 + rl] = __float2half_rn(v1);
                }
                s += __shfl_xor_sync(0xffffffffu, s, 1);
                s += __shfl_xor_sync(0xffffffffu, s, 2);
                d += __shfl_xor_sync(0xffffffffu, d, 1);
                d += __shfl_xor_sync(0xffffffffu, d, 2);
                if (tig == 0) {
                    svp[wn * 128 + rl] = s;
                    dvp[wn * 128 + rl] = d;
                }
            }
        }
        __syncthreads();

        // reduce partials (scaled by log2e) -> sv / dv / smaxs
        if (tid < 256) {
            int hh = tid >> 7, j = tid & 127;
            sv[hh * 128 + j] = (svp[(2 * hh) * 128 + j]
                                + svp[(2 * hh + 1) * 128 + j]) * LOG2E;
            dv[hh * 128 + j] = (dvp[(2 * hh) * 128 + j]
                                + dvp[(2 * hh + 1) * 128 + j]) * LOG2E;
        } else if (tid < 320) {
            int t = tid - 256, hh = t >> 5, l = t & 31;
            float m = -1e30f;
#pragma unroll
            for (int q = 0; q < 4; q++) {
                int j = l + q * 32;
                m = fmaxf(m, svp[(2 * hh) * 128 + j]
                             + svp[(2 * hh + 1) * 128 + j]);
            }
#pragma unroll
            for (int off = 16; off; off >>= 1)
                m = fmaxf(m, __shfl_xor_sync(0xffffffffu, m, off));
            if (l == 0) smaxs[hh] = m * LOG2E;
        }
        __syncthreads();

        // ---------------- attention: 16x64 warp tiles, fp16 MMA ------------
        {
            const int gh = nh * 2 + hl;
            const uint32_t ht_b = sb + OFF_U + (uint32_t)hl * (64 * HPITCH);
            const float* svh = sv + hl * 128;

            const int rr0 = wm8 * 16 + gid;
            const float dd0 = dv[hl * 128 + rr0];
            const float dd1 = dv[hl * 128 + rr0 + 8];
            const float smx = smaxs[hl];
            const float mx0 = leaky(smx + dd0);   // exact row max (monotone)
            const float mx1 = leaky(smx + dd1);

            if (!last) {
                float oacc[8][4];
#pragma unroll
                for (int nt = 0; nt < 8; nt++)
#pragma unroll
                    for (int c = 0; c < 4; c++) oacc[nt][c] = 0.f;
                float sum0 = 0.f, sum1 = 0.f;

#pragma unroll
                for (int kk = 0; kk < 8; kk++) {   // k16 blocks over j
                    float2 sjA = *(const float2*)&svh[kk * 16 + tig * 2];
                    float2 sjB = *(const float2*)&svh[kk * 16 + tig * 2 + 8];
                    float p00 = ex2(leaky(sjA.x + dd0) - mx0);
                    float p01 = ex2(leaky(sjA.y + dd0) - mx0);
                    float p10 = ex2(leaky(sjA.x + dd1) - mx1);
                    float p11 = ex2(leaky(sjA.y + dd1) - mx1);
                    float p02 = ex2(leaky(sjB.x + dd0) - mx0);
                    float p03 = ex2(leaky(sjB.y + dd0) - mx0);
                    float p12 = ex2(leaky(sjB.x + dd1) - mx1);
                    float p13 = ex2(leaky(sjB.y + dd1) - mx1);
                    sum0 += p00 + p01 + p02 + p03;
                    sum1 += p10 + p11 + p12 + p13;
                    uint32_t a0 = h2pack(p00, p01);
                    uint32_t a1 = h2pack(p10, p11);
                    uint32_t a2 = h2pack(p02, p03);
                    uint32_t a3 = h2pack(p12, p13);
#pragma unroll
                    for (int pr = 0; pr < 4; pr++) {
                        uint32_t b0, b1, b2, b3;
                        ldsm_x4(b0, b1, b2, b3,
                                ht_b + pr * (16 * HPITCH) + hoffA + kk * 32);
                        mma_f16(oacc[pr * 2][0], oacc[pr * 2][1],
                                oacc[pr * 2][2], oacc[pr * 2][3],
                                a0, a1, a2, a3, b0, b1);
                        mma_f16(oacc[pr * 2 + 1][0], oacc[pr * 2 + 1][1],
                                oacc[pr * 2 + 1][2], oacc[pr * 2 + 1][3],
                                a0, a1, a2, a3, b2, b3);
                    }
                }
                sum0 += __shfl_xor_sync(0xffffffffu, sum0, 1);
                sum0 += __shfl_xor_sync(0xffffffffu, sum0, 2);
                sum1 += __shfl_xor_sync(0xffffffffu, sum1, 1);
                sum1 += __shfl_xor_sync(0xffffffffu, sum1, 2);
                float inv0 = 1.0f / sum0, inv1 = 1.0f / sum1;

                __half* o0 = X + ((size_t)m0 + rr0) * 256 + gh * 64;
                __half* o1 = X + ((size_t)m0 + rr0 + 8) * 256 + gh * 64;
#pragma unroll
                for (int nt = 0; nt < 8; nt++) {
                    int col = nt * 8 + tig * 2;
                    float bb0 = biass[gh * 64 + col];
                    float bb1 = biass[gh * 64 + col + 1];
                    *(__half2*)&o0[col] = __floats2half2_rn(
                        fmaf(oacc[nt][0], inv0, bb0),
                        fmaf(oacc[nt][1], inv0, bb1));
                    *(__half2*)&o1[col] = __floats2half2_rn(
                        fmaf(oacc[nt][2], inv1, bb0),
                        fmaf(oacc[nt][3], inv1, bb1));
                }
            } else {
                // q path: q_j = sum_i e_ij / r_i (no MMA)
                float sum0 = 0.f, sum1 = 0.f;
#pragma unroll
                for (int kk = 0; kk < 8; kk++) {
                    float2 sjA = *(const float2*)&svh[kk * 16 + tig * 2];
                    float2 sjB = *(const float2*)&svh[kk * 16 + tig * 2 + 8];
                    sum0 += ex2(leaky(sjA.x + dd0) - mx0)
                          + ex2(leaky(sjA.y + dd0) - mx0)
                          + ex2(leaky(sjB.x + dd0) - mx0)
                          + ex2(leaky(sjB.y + dd0) - mx0);
                    sum1 += ex2(leaky(sjA.x + dd1) - mx1)
                          + ex2(leaky(sjA.y + dd1) - mx1)
                          + ex2(leaky(sjB.x + dd1) - mx1)
                          + ex2(leaky(sjB.y + dd1) - mx1);
                }
                sum0 += __shfl_xor_sync(0xffffffffu, sum0, 1);
                sum0 += __shfl_xor_sync(0xffffffffu, sum0, 2);
                sum1 += __shfl_xor_sync(0xffffffffu, sum1, 1);
                sum1 += __shfl_xor_sync(0xffffffffu, sum1, 2);
                float inv0 = 1.0f / sum0, inv1 = 1.0f / sum1;

#pragma unroll
                for (int kk = 0; kk < 8; kk++) {
                    float2 sjA = *(const float2*)&svh[kk * 16 + tig * 2];
                    float2 sjB = *(const float2*)&svh[kk * 16 + tig * 2 + 8];
                    float q0 = ex2(leaky(sjA.x + dd0) - mx0) * inv0
                             + ex2(leaky(sjA.x + dd1) - mx1) * inv1;
                    float q1 = ex2(leaky(sjA.y + dd0) - mx0) * inv0
                             + ex2(leaky(sjA.y + dd1) - mx1) * inv1;
                    float q2 = ex2(leaky(sjB.x + dd0) - mx0) * inv0
                             + ex2(leaky(sjB.x + dd1) - mx1) * inv1;
                    float q3 = ex2(leaky(sjB.y + dd0) - mx0) * inv0
                             + ex2(leaky(sjB.y + dd1) - mx1) * inv1;
#pragma unroll
                    for (int off = 4; off < 32; off <<= 1) {
                        q0 += __shfl_xor_sync(0xffffffffu, q0, off);
                        q1 += __shfl_xor_sync(0xffffffffu, q1, off);
                        q2 += __shfl_xor_sync(0xffffffffu, q2, off);
                        q3 += __shfl_xor_sync(0xffffffffu, q3, off);
                    }
                    if (gid == 0) {
                        int jb = kk * 16 + tig * 2;
                        qpart[(hl * 8 + wm8) * 128 + jb]     = q0;
                        qpart[(hl * 8 + wm8) * 128 + jb + 1] = q1;
                        qpart[(hl * 8 + wm8) * 128 + jb + 8] = q2;
                        qpart[(hl * 8 + wm8) * 128 + jb + 9] = q3;
                    }
                }
            }
        }

        if (last) {
            __syncthreads();
            if (tid < 256) {
                int hh = tid >> 7, cc = tid & 127;
                float qs = 0.f;
#pragma unroll
                for (int w = 0; w < 8; w++)
                    qs += qpart[(hh * 8 + w) * 128 + cc];
                qv[hh * 128 + cc] = qs;
            }
            __syncthreads();
#pragma unroll 1
            for (int hq = 0; hq < 2; hq++) {
                int c = tid >> 3, t8 = tid & 7;
                float a3 = 0.f;
#pragma unroll 4
                for (int jj = 0; jj < 16; jj++) {
                    int j = t8 * 16 + jj;
                    a3 += qv[hq * 128 + j] *
                          __half2float(Ht16[(hq * 64 + c) * 136 + j]);
                }
                a3 += __shfl_xor_sync(0xffffffffu, a3, 1);
                a3 += __shfl_xor_sync(0xffffffffu, a3, 2);
                a3 += __shfl_xor_sync(0xffffffffu, a3, 4);
                int gho = nh * 2 + hq;
                if (t8 == 0)
                    out_final[(size_t)b * 256 + gho * 64 + c] =
                        a3 + 128.f * biass[gho * 64 + c];
            }
        }
        __syncthreads();   // Ht dead; next half may overwrite staging
    } // nh
}

// ---------------------------------------------------------------------------
extern "C" void kernel_launch(void* const* d_in, const int* in_sizes, int n_in,
                              void* d_out, int out_size)
{
    const float* x = (const float*)d_in[0];
    const float* W[3]    = {(const float*)d_in[2], (const float*)d_in[6],  (const float*)d_in[10]};
    const float* asv[3]  = {(const float*)d_in[3], (const float*)d_in[7],  (const float*)d_in[11]};
    const float* adv[3]  = {(const float*)d_in[4], (const float*)d_in[8],  (const float*)d_in[12]};
    const float* bias[3] = {(const float*)d_in[5], (const float*)d_in[9],  (const float*)d_in[13]};

    __half *pX, *pY, *pWt;
    cudaGetSymbolAddress((void**)&pX, g_X);
    cudaGetSymbolAddress((void**)&pY, g_Y);
    cudaGetSymbolAddress((void**)&pWt, g_Wt);

    cudaFuncSetAttribute(layer_kernel,
                         cudaFuncAttributeMaxDynamicSharedMemorySize, LAYER_SMEM);

    transpose_all_kernel<<<640, 256>>>(W[0], W[1], W[2], pWt);
    round_x_kernel<<<8192, 256>>>(x, pY);

    // layer 0: g_Y(xr) -> g_X ; layer 1: g_X -> g_Y ; layer 2: g_Y -> d_out
    const __half* in_buf[3]  = {pY, pX, pY};
    __half*       out_buf[3] = {pX, pY, nullptr};

    for (int l = 0; l < 3; l++) {
        const int K = (l == 0) ? 128 : 256;
        const __half* Wtl = pWt + (size_t)l * 65536;
        layer_kernel<<<512, 512, LAYER_SMEM>>>(
            in_buf[l], Wtl, asv[l], adv[l], bias[l],
            out_buf[l], (float*)d_out, K, l == 2);
    }
}

// round 15
// speedup vs baseline: 1.4094x; 1.0221x over previous
#include <cuda_runtime.h>
#include <cuda_fp16.h>
#include <cstdint>
#include <math.h>

#define B_GRAPHS 512
#define N_NODES  128
#define F_OUT    256
#define HEADS    4
#define HID      64
#define M_TOT    (B_GRAPHS * N_NODES)   // 65536
#define LOG2E    1.4426950408889634f

__device__ __half g_X[(size_t)M_TOT * F_OUT];
__device__ __half g_Y[(size_t)M_TOT * F_OUT];
__device__ __half g_Wt[3][256 * 256];

// ---------------------------------------------------------------------------
#define CP_ASYNC16(dst, src) \
    asm volatile("cp.async.cg.shared.global [%0], [%1], 16;" \
        :: "r"((uint32_t)(dst)), "l"(src) : "memory")
#define CP_COMMIT() asm volatile("cp.async.commit_group;" ::: "memory")
#define CP_WAIT1()  asm volatile("cp.async.wait_group 1;" ::: "memory")
#define CP_WAIT0()  asm volatile("cp.async.wait_group 0;" ::: "memory")

__device__ __forceinline__ uint32_t smem_to_u32(const void* p) {
    uint32_t a;
    asm("{ .reg .u64 t; cvta.to.shared.u64 t, %1; cvt.u32.u64 %0, t; }"
        : "=r"(a) : "l"(p));
    return a;
}

__device__ __forceinline__ float ex2(float x) {
    float r;
    asm("ex2.approx.f32 %0, %1;" : "=f"(r) : "f"(x));
    return r;
}

__device__ __forceinline__ uint32_t h2pack(float lo, float hi) {
    uint32_t d;
    asm("cvt.rn.f16x2.f32 %0, %1, %2;" : "=r"(d) : "f"(hi), "f"(lo));
    return d;
}

__device__ __forceinline__ void ldsm_x4(
    uint32_t& r0, uint32_t& r1, uint32_t& r2, uint32_t& r3, uint32_t addr)
{
    asm volatile("ldmatrix.sync.aligned.m8n8.x4.shared.b16 {%0,%1,%2,%3}, [%4];"
        : "=r"(r0), "=r"(r1), "=r"(r2), "=r"(r3) : "r"(addr));
}

__device__ __forceinline__ void mma_f16(
    float& d0, float& d1, float& d2, float& d3,
    uint32_t a0, uint32_t a1, uint32_t a2, uint32_t a3,
    uint32_t b0, uint32_t b1)
{
    asm volatile(
        "mma.sync.aligned.m16n8k16.row.col.f32.f16.f16.f32 "
        "{%0,%1,%2,%3}, {%4,%5,%6,%7}, {%8,%9}, {%0,%1,%2,%3};"
        : "+f"(d0), "+f"(d1), "+f"(d2), "+f"(d3)
        : "r"(a0), "r"(a1), "r"(a2), "r"(a3), "r"(b0), "r"(b1));
}

__device__ __forceinline__ float leaky(float a) {
    return fmaxf(a, 0.2f * a);
}

// ---------------------------------------------------------------------------
__global__ __launch_bounds__(256) void round_x_kernel(
    const float* __restrict__ x, __half* __restrict__ xr)
{
    int t = blockIdx.x * 256 + threadIdx.x;
    float4 v = ((const float4*)x)[t];
    __half2* o = (__half2*)xr;
    o[t * 2]     = __floats2half2_rn(v.x, v.y);
    o[t * 2 + 1] = __floats2half2_rn(v.z, v.w);
}

__global__ __launch_bounds__(256) void transpose_all_kernel(
    const float* __restrict__ W0, const float* __restrict__ W1,
    const float* __restrict__ W2, __half* __restrict__ Wt)
{
    int t = blockIdx.x * 256 + threadIdx.x;
    if (t < 128 * 256) {
        int k = t >> 8, n = t & 255;
        Wt[(size_t)n * 128 + k] = __float2half_rn(W0[t]);
    } else if (t < 128 * 256 + 256 * 256) {
        int t2 = t - 128 * 256;
        int k = t2 >> 8, n = t2 & 255;
        Wt[65536 + (size_t)n * 256 + k] = __float2half_rn(W1[t2]);
    } else {
        int t3 = t - 128 * 256 - 256 * 256;
        int k = t3 >> 8, n = t3 & 255;
        Wt[131072 + (size_t)n * 256 + k] = __float2half_rn(W2[t3]);
    }
}

// ===========================================================================
// Fused layer kernel, fp16 MMA, 512 thr, 2 CTAs/SM.
// 3-stage SW128-swizzled cp.async pipeline (prefetch distance 2).
// ===========================================================================
#define HPITCH 272                    // Ht row pitch bytes (136 halves)
#define OFF_SVP  3072                 // [4][128] f32 partials
#define OFF_DVP  5120
#define OFF_SV   7168                 // [2][128] f32 scaled scores
#define OFF_DV   8192
#define OFF_SMX  9216                 // [2]
#define OFF_QV   9472                 // [2][128]
#define OFF_U    10496                // 128B aligned
#define A_STG    16384                // 128 rows x 128B, SW128-swizzled
#define OFF_BSTG (OFF_U + 3 * A_STG)  // B stages after 3 A stages
#define OFF_QP   (OFF_U + 34816)      // [16][128] f32, after Ht, in dead stages
#define LAYER_SMEM (OFF_U + 6 * A_STG)   // 108800 -> 2 CTAs/SM
// Ht: 128 cols x 272B = 34816 B, overlaps A stages (dead during attention).

__global__ __launch_bounds__(512, 2) void layer_kernel(
    const __half* __restrict__ A, const __half* __restrict__ Wt,
    const float* __restrict__ att_src, const float* __restrict__ att_dst,
    const float* __restrict__ bias_g,
    __half* __restrict__ X, float* __restrict__ out_final,
    int K, int last)
{
    extern __shared__ char sm[];
    uint32_t sb = smem_to_u32(sm);
    float* atts  = (float*)(sm);
    float* attd  = (float*)(sm + 1024);
    float* biass = (float*)(sm + 2048);
    float* svp   = (float*)(sm + OFF_SVP);
    float* dvp   = (float*)(sm + OFF_DVP);
    float* sv    = (float*)(sm + OFF_SV);
    float* dv    = (float*)(sm + OFF_DV);
    float* smaxs = (float*)(sm + OFF_SMX);
    float* qv    = (float*)(sm + OFF_QV);
    float* qpart = (float*)(sm + OFF_QP);
    __half* Ht16 = (__half*)(sm + OFF_U);

    const int tid = threadIdx.x;
    const int warp = tid >> 5, lane = tid & 31;
    const int gid = lane >> 2, tig = lane & 3;
    const int wm = warp & 3, wn = warp >> 2;
    const int b = blockIdx.x, m0 = b * 128;
    const int t4 = lane >> 3, r8 = lane & 7;

    if (tid < 256) {
        atts[tid]  = att_src[tid];
        attd[tid]  = att_dst[tid];
        biass[tid] = bias_g[tid];
    }

    // GEMM fragment row bases (SW128 staging: 128B rows, chunk ^= r8)
    const uint32_t abase0 = (uint32_t)((wm * 32 + (t4 & 1) * 8 + r8) * 128);
    const uint32_t bbase0 = (uint32_t)((wn * 32 + (t4 >> 1) * 8 + r8) * 128);
    const int cbA = t4 >> 1, cbB = t4 & 1;

    // attention: warp = (hl head, wm8 row-group); 16 rows x 64 cols
    const int wm8 = warp & 7, hl = warp >> 3;
    const uint32_t hoffA = (uint32_t)(((t4 >> 1) * 8 + r8) * HPITCH
                                      + (t4 & 1) * 16);

    const int NC = K >> 6;     // chunks of 64 k

#pragma unroll 1
    for (int nh = 0; nh < 2; nh++) {
        // ---------------- GEMM half: 128 x 128 (fp16) ----------------
        float acc[2][4][4];
#pragma unroll
        for (int mt = 0; mt < 2; mt++)
#pragma unroll
            for (int nt = 0; nt < 4; nt++)
#pragma unroll
                for (int c = 0; c < 4; c++) acc[mt][nt][c] = 0.f;

        auto load_chunk = [&](int k0, int stage) {
            uint32_t ab = sb + OFF_U + stage * A_STG;
            uint32_t bb = sb + OFF_BSTG + stage * A_STG;
#pragma unroll
            for (int i = 0; i < 2; i++) {
                int g = tid + i * 512;
                int row = g >> 3, c = g & 7;
                uint32_t doff = (uint32_t)(row * 128 + ((c ^ (row & 7)) << 4));
                CP_ASYNC16(ab + doff,
                           A + (size_t)(m0 + row) * K + k0 + c * 8);
            }
#pragma unroll
            for (int i = 0; i < 2; i++) {
                int g = tid + i * 512;
                int row = g >> 3, c = g & 7;
                uint32_t doff = (uint32_t)(row * 128 + ((c ^ (row & 7)) << 4));
                CP_ASYNC16(bb + doff,
                           Wt + (size_t)(nh * 128 + row) * K + k0 + c * 8);
            }
        };

        load_chunk(0, 0);
        CP_COMMIT();
        if (NC > 1) { load_chunk(64, 1); CP_COMMIT(); }

        // 3-stage pipeline, prefetch distance 2:
        //   WAIT(chunk c done) -> barrier -> issue chunk c+2 -> MMA(c)
        for (int c = 0; c < NC; c++) {
            if (c + 1 < NC) CP_WAIT1(); else CP_WAIT0();
            __syncthreads();
            if (c + 2 < NC) {
                load_chunk((c + 2) << 6, (c + 2) % 3);
                CP_COMMIT();
            }

            uint32_t as_b = sb + OFF_U + (c % 3) * A_STG;
            uint32_t bs_b = sb + OFF_BSTG + (c % 3) * A_STG;
#pragma unroll
            for (int kk = 0; kk < 4; kk++) {
                uint32_t offA = (uint32_t)((((kk << 1) | cbA) ^ r8) << 4);
                uint32_t offB = (uint32_t)((((kk << 1) | cbB) ^ r8) << 4);
                uint32_t a[2][4];
#pragma unroll
                for (int mt = 0; mt < 2; mt++)
                    ldsm_x4(a[mt][0], a[mt][1], a[mt][2], a[mt][3],
                            as_b + abase0 + mt * 2048 + offA);
                uint32_t bf[4][2];
#pragma unroll
                for (int pr = 0; pr < 2; pr++)
                    ldsm_x4(bf[pr * 2][0], bf[pr * 2][1],
                            bf[pr * 2 + 1][0], bf[pr * 2 + 1][1],
                            bs_b + bbase0 + pr * 2048 + offB);
#pragma unroll
                for (int mt = 0; mt < 2; mt++)
#pragma unroll
                    for (int nt = 0; nt < 4; nt++)
                        mma_f16(acc[mt][nt][0], acc[mt][nt][1],
                                acc[mt][nt][2], acc[mt][nt][3],
                                a[mt][0], a[mt][1], a[mt][2], a[mt][3],
                                bf[nt][0], bf[nt][1]);
            }
        }
        __syncthreads();   // stage reads done before Ht overwrites U

        // ---------------- epilogue: Ht (fp16, transposed) + scores ---------
        const int hl_w = wn >> 1;
#pragma unroll
        for (int mt = 0; mt < 2; mt++) {
#pragma unroll
            for (int h2 = 0; h2 < 2; h2++) {
                int rl = wm * 32 + mt * 16 + gid + 8 * h2;
                float s = 0.f, d = 0.f;
#pragma unroll
                for (int nt = 0; nt < 4; nt++) {
                    int cl = (wn & 1) * 32 + nt * 8 + tig * 2;
                    int gc = nh * 128 + wn * 32 + nt * 8 + tig * 2;
                    float v0 = acc[mt][nt][h2 * 2], v1 = acc[mt][nt][h2 * 2 + 1];
                    s = fmaf(v0, atts[gc], s);  s = fmaf(v1, atts[gc + 1], s);
                    d = fmaf(v0, attd[gc], d);  d = fmaf(v1, attd[gc + 1], d);
                    Ht16[(hl_w * 64 + cl) * 136 + rl]     = __float2half_rn(v0);
                    Ht16[(hl_w * 64 + cl + 1) * 136 + rl] = __float2half_rn(v1);
                }
                s += __shfl_xor_sync(0xffffffffu, s, 1);
                s += __shfl_xor_sync(0xffffffffu, s, 2);
                d += __shfl_xor_sync(0xffffffffu, d, 1);
                d += __shfl_xor_sync(0xffffffffu, d, 2);
                if (tig == 0) {
                    svp[wn * 128 + rl] = s;
                    dvp[wn * 128 + rl] = d;
                }
            }
        }
        __syncthreads();

        // reduce partials (scaled by log2e) -> sv / dv / smaxs
        if (tid < 256) {
            int hh = tid >> 7, j = tid & 127;
            sv[hh * 128 + j] = (svp[(2 * hh) * 128 + j]
                                + svp[(2 * hh + 1) * 128 + j]) * LOG2E;
            dv[hh * 128 + j] = (dvp[(2 * hh) * 128 + j]
                                + dvp[(2 * hh + 1) * 128 + j]) * LOG2E;
        } else if (tid < 320) {
            int t = tid - 256, hh = t >> 5, l = t & 31;
            float m = -1e30f;
#pragma unroll
            for (int q = 0; q < 4; q++) {
                int j = l + q * 32;
                m = fmaxf(m, svp[(2 * hh) * 128 + j]
                             + svp[(2 * hh + 1) * 128 + j]);
            }
#pragma unroll
            for (int off = 16; off; off >>= 1)
                m = fmaxf(m, __shfl_xor_sync(0xffffffffu, m, off));
            if (l == 0) smaxs[hh] = m * LOG2E;
        }
        __syncthreads();

        // ---------------- attention: 16x64 warp tiles, fp16 MMA ------------
        {
            const int gh = nh * 2 + hl;
            const uint32_t ht_b = sb + OFF_U + (uint32_t)hl * (64 * HPITCH);
            const float* svh = sv + hl * 128;

            const int rr0 = wm8 * 16 + gid;
            const float dd0 = dv[hl * 128 + rr0];
            const float dd1 = dv[hl * 128 + rr0 + 8];
            const float smx = smaxs[hl];
            const float mx0 = leaky(smx + dd0);
            const float mx1 = leaky(smx + dd1);

            if (!last) {
                float oacc[8][4];
#pragma unroll
                for (int nt = 0; nt < 8; nt++)
#pragma unroll
                    for (int c = 0; c < 4; c++) oacc[nt][c] = 0.f;
                float sum0 = 0.f, sum1 = 0.f;

#pragma unroll
                for (int kk = 0; kk < 8; kk++) {
                    float2 sjA = *(const float2*)&svh[kk * 16 + tig * 2];
                    float2 sjB = *(const float2*)&svh[kk * 16 + tig * 2 + 8];
                    float p00 = ex2(leaky(sjA.x + dd0) - mx0);
                    float p01 = ex2(leaky(sjA.y + dd0) - mx0);
                    float p10 = ex2(leaky(sjA.x + dd1) - mx1);
                    float p11 = ex2(leaky(sjA.y + dd1) - mx1);
                    float p02 = ex2(leaky(sjB.x + dd0) - mx0);
                    float p03 = ex2(leaky(sjB.y + dd0) - mx0);
                    float p12 = ex2(leaky(sjB.x + dd1) - mx1);
                    float p13 = ex2(leaky(sjB.y + dd1) - mx1);
                    sum0 += p00 + p01 + p02 + p03;
                    sum1 += p10 + p11 + p12 + p13;
                    uint32_t a0 = h2pack(p00, p01);
                    uint32_t a1 = h2pack(p10, p11);
                    uint32_t a2 = h2pack(p02, p03);
                    uint32_t a3 = h2pack(p12, p13);
#pragma unroll
                    for (int pr = 0; pr < 4; pr++) {
                        uint32_t b0, b1, b2, b3;
                        ldsm_x4(b0, b1, b2, b3,
                                ht_b + pr * (16 * HPITCH) + hoffA + kk * 32);
                        mma_f16(oacc[pr * 2][0], oacc[pr * 2][1],
                                oacc[pr * 2][2], oacc[pr * 2][3],
                                a0, a1, a2, a3, b0, b1);
                        mma_f16(oacc[pr * 2 + 1][0], oacc[pr * 2 + 1][1],
                                oacc[pr * 2 + 1][2], oacc[pr * 2 + 1][3],
                                a0, a1, a2, a3, b2, b3);
                    }
                }
                sum0 += __shfl_xor_sync(0xffffffffu, sum0, 1);
                sum0 += __shfl_xor_sync(0xffffffffu, sum0, 2);
                sum1 += __shfl_xor_sync(0xffffffffu, sum1, 1);
                sum1 += __shfl_xor_sync(0xffffffffu, sum1, 2);
                float inv0 = 1.0f / sum0, inv1 = 1.0f / sum1;

                __half* o0 = X + ((size_t)m0 + rr0) * 256 + gh * 64;
                __half* o1 = X + ((size_t)m0 + rr0 + 8) * 256 + gh * 64;
#pragma unroll
                for (int nt = 0; nt < 8; nt++) {
                    int col = nt * 8 + tig * 2;
                    float bb0 = biass[gh * 64 + col];
                    float bb1 = biass[gh * 64 + col + 1];
                    *(__half2*)&o0[col] = __floats2half2_rn(
                        fmaf(oacc[nt][0], inv0, bb0),
                        fmaf(oacc[nt][1], inv0, bb1));
                    *(__half2*)&o1[col] = __floats2half2_rn(
                        fmaf(oacc[nt][2], inv1, bb0),
                        fmaf(oacc[nt][3], inv1, bb1));
                }
            } else {
                // q path: q_j = sum_i e_ij / r_i (no MMA)
                float sum0 = 0.f, sum1 = 0.f;
#pragma unroll
                for (int kk = 0; kk < 8; kk++) {
                    float2 sjA = *(const float2*)&svh[kk * 16 + tig * 2];
                    float2 sjB = *(const float2*)&svh[kk * 16 + tig * 2 + 8];
                    sum0 += ex2(leaky(sjA.x + dd0) - mx0)
                          + ex2(leaky(sjA.y + dd0) - mx0)
                          + ex2(leaky(sjB.x + dd0) - mx0)
                          + ex2(leaky(sjB.y + dd0) - mx0);
                    sum1 += ex2(leaky(sjA.x + dd1) - mx1)
                          + ex2(leaky(sjA.y + dd1) - mx1)
                          + ex2(leaky(sjB.x + dd1) - mx1)
                          + ex2(leaky(sjB.y + dd1) - mx1);
                }
                sum0 += __shfl_xor_sync(0xffffffffu, sum0, 1);
                sum0 += __shfl_xor_sync(0xffffffffu, sum0, 2);
                sum1 += __shfl_xor_sync(0xffffffffu, sum1, 1);
                sum1 += __shfl_xor_sync(0xffffffffu, sum1, 2);
                float inv0 = 1.0f / sum0, inv1 = 1.0f / sum1;

#pragma unroll
                for (int kk = 0; kk < 8; kk++) {
                    float2 sjA = *(const float2*)&svh[kk * 16 + tig * 2];
                    float2 sjB = *(const float2*)&svh[kk * 16 + tig * 2 + 8];
                    float q0 = ex2(leaky(sjA.x + dd0) - mx0) * inv0
                             + ex2(leaky(sjA.x + dd1) - mx1) * inv1;
                    float q1 = ex2(leaky(sjA.y + dd0) - mx0) * inv0
                             + ex2(leaky(sjA.y + dd1) - mx1) * inv1;
                    float q2 = ex2(leaky(sjB.x + dd0) - mx0) * inv0
                             + ex2(leaky(sjB.x + dd1) - mx1) * inv1;
                    float q3 = ex2(leaky(sjB.y + dd0) - mx0) * inv0
                             + ex2(leaky(sjB.y + dd1) - mx1) * inv1;
#pragma unroll
                    for (int off = 4; off < 32; off <<= 1) {
                        q0 += __shfl_xor_sync(0xffffffffu, q0, off);
                        q1 += __shfl_xor_sync(0xffffffffu, q1, off);
                        q2 += __shfl_xor_sync(0xffffffffu, q2, off);
                        q3 += __shfl_xor_sync(0xffffffffu, q3, off);
                    }
                    if (gid == 0) {
                        int jb = kk * 16 + tig * 2;
                        qpart[(hl * 8 + wm8) * 128 + jb]     = q0;
                        qpart[(hl * 8 + wm8) * 128 + jb + 1] = q1;
                        qpart[(hl * 8 + wm8) * 128 + jb + 8] = q2;
                        qpart[(hl * 8 + wm8) * 128 + jb + 9] = q3;
                    }
                }
            }
        }

        if (last) {
            __syncthreads();
            if (tid < 256) {
                int hh = tid >> 7, cc = tid & 127;
                float qs = 0.f;
#pragma unroll
                for (int w = 0; w < 8; w++)
                    qs += qpart[(hh * 8 + w) * 128 + cc];
                qv[hh * 128 + cc] = qs;
            }
            __syncthreads();
#pragma unroll 1
            for (int hq = 0; hq < 2; hq++) {
                int c = tid >> 3, t8 = tid & 7;
                float a3 = 0.f;
#pragma unroll 4
                for (int jj = 0; jj < 16; jj++) {
                    int j = t8 * 16 + jj;
                    a3 += qv[hq * 128 + j] *
                          __half2float(Ht16[(hq * 64 + c) * 136 + j]);
                }
                a3 += __shfl_xor_sync(0xffffffffu, a3, 1);
                a3 += __shfl_xor_sync(0xffffffffu, a3, 2);
                a3 += __shfl_xor_sync(0xffffffffu, a3, 4);
                int gho = nh * 2 + hq;
                if (t8 == 0)
                    out_final[(size_t)b * 256 + gho * 64 + c] =
                        a3 + 128.f * biass[gho * 64 + c];
            }
        }
        __syncthreads();   // Ht dead; next half may overwrite staging
    } // nh
}

// ---------------------------------------------------------------------------
extern "C" void kernel_launch(void* const* d_in, const int* in_sizes, int n_in,
                              void* d_out, int out_size)
{
    const float* x = (const float*)d_in[0];
    const float* W[3]    = {(const float*)d_in[2], (const float*)d_in[6],  (const float*)d_in[10]};
    const float* asv[3]  = {(const float*)d_in[3], (const float*)d_in[7],  (const float*)d_in[11]};
    const float* adv[3]  = {(const float*)d_in[4], (const float*)d_in[8],  (const float*)d_in[12]};
    const float* bias[3] = {(const float*)d_in[5], (const float*)d_in[9],  (const float*)d_in[13]};

    __half *pX, *pY, *pWt;
    cudaGetSymbolAddress((void**)&pX, g_X);
    cudaGetSymbolAddress((void**)&pY, g_Y);
    cudaGetSymbolAddress((void**)&pWt, g_Wt);

    cudaFuncSetAttribute(layer_kernel,
                         cudaFuncAttributeMaxDynamicSharedMemorySize, LAYER_SMEM);

    transpose_all_kernel<<<640, 256>>>(W[0], W[1], W[2], pWt);
    round_x_kernel<<<8192, 256>>>(x, pY);

    // layer 0: g_Y(xr) -> g_X ; layer 1: g_X -> g_Y ; layer 2: g_Y -> d_out
    const __half* in_buf[3]  = {pY, pX, pY};
    __half*       out_buf[3] = {pX, pY, nullptr};

    for (int l = 0; l < 3; l++) {
        const int K = (l == 0) ? 128 : 256;
        const __half* Wtl = pWt + (size_t)l * 65536;
        layer_kernel<<<512, 512, LAYER_SMEM>>>(
            in_buf[l], Wtl, asv[l], adv[l], bias[l],
            out_buf[l], (float*)d_out, K, l == 2);
    }
}